// round 16
// baseline (speedup 1.0000x reference)
#include <cuda_runtime.h>
#include <cuda_bf16.h>
#include <mma.h>
#include <math.h>
#include <cstdint>

using namespace nvcuda;

#define T_STEPS 128
#define BATCH   32
#define HIDDEN  1024
#define GATES   4096     // 4*HIDDEN
#define NCLS    32000
#define M_ALL   4096     // T_STEPS*BATCH

// ---------------- scratch (~96 MiB, within the passing regime) ----------------
__device__ float g_XG[(size_t)M_ALL * GATES];   // 64 MB
__device__ float g_c[BATCH * HIDDEN];
__device__ unsigned g_arrive;                   // grid-barrier counter
__device__ __align__(128) __nv_bfloat16 g_hh[BATCH * HIDDEN];
__device__ __align__(128) __nv_bfloat16 g_hl[BATCH * HIDDEN];
__device__ __align__(128) __nv_bfloat16 g_HSh[(size_t)M_ALL * HIDDEN];  // 8 MB
__device__ __align__(128) __nv_bfloat16 g_HSl[(size_t)M_ALL * HIDDEN];  // 8 MB
__device__ __align__(128) __nv_bfloat16 g_WhPH[(size_t)HIDDEN * GATES]; // 8 MB (permuted)
__device__ __align__(128) __nv_bfloat16 g_WhPL[(size_t)HIDDEN * GATES]; // 8 MB (permuted)

// ---------------- helpers: packed fp32x4 -> bf16x2 hi/lo ----------------
__device__ __forceinline__ void split4(const float4 v, uint2& hi, uint2& lo) {
    __nv_bfloat162 h01 = __floats2bfloat162_rn(v.x, v.y);
    __nv_bfloat162 h23 = __floats2bfloat162_rn(v.z, v.w);
    float2 f01 = __bfloat1622float2(h01);
    float2 f23 = __bfloat1622float2(h23);
    __nv_bfloat162 l01 = __floats2bfloat162_rn(v.x - f01.x, v.y - f01.y);
    __nv_bfloat162 l23 = __floats2bfloat162_rn(v.z - f23.x, v.w - f23.y);
    hi.x = *(uint32_t*)&h01; hi.y = *(uint32_t*)&h23;
    lo.x = *(uint32_t*)&l01; lo.y = *(uint32_t*)&l23;
}

// ---------------- init: zero state + barrier counter ----------------
__global__ void init_state_kernel() {
    int i = blockIdx.x * blockDim.x + threadIdx.x;
    if (i == 0) g_arrive = 0u;
    if (i < BATCH * HIDDEN) {
        g_c[i] = 0.0f;
        g_hh[i] = __float2bfloat16(0.0f);
        g_hl[i] = __float2bfloat16(0.0f);
    }
}

// ---------------- split + permute Wh: WhP[k][c*32+g*8+u] = Wh[k][c*8+u+g*1024]
__global__ void split_wh_perm_kernel(const float* __restrict__ Wh) {
    int idx = blockIdx.x * 256 + threadIdx.x;   // 0 .. 1024*512-1
    int k = idx >> 9;          // 0..1023
    int grp = idx & 511;       // output group of 8 cols
    int c = grp >> 2, g = grp & 3;
    const float* src = Wh + (size_t)k * GATES + c * 8 + g * 1024;
    float4 v0 = *(const float4*)(src);
    float4 v1 = *(const float4*)(src + 4);
    uint2 h0, l0, h1, l1;
    split4(v0, h0, l0);
    split4(v1, h1, l1);
    uint4 hv; hv.x = h0.x; hv.y = h0.y; hv.z = h1.x; hv.w = h1.y;
    uint4 lv; lv.x = l0.x; lv.y = l0.y; lv.z = l1.x; lv.w = l1.y;
    size_t o = (size_t)k * GATES + grp * 8;
    *(uint4*)(g_WhPH + o) = hv;
    *(uint4*)(g_WhPL + o) = lv;
}

// ==================== wmma GEMM constants =========================
#define PBK   32
#define ASTR  40      // A smem row stride (elements)
#define BSTR  136     // B smem row stride (elements)

// ---- embed (R14-proven): XG = emb[ids] @ Wx + b ---------------------------
__global__ void __launch_bounds__(256, 1)
gemm_wmma_embed(const int* __restrict__ ids, const float* __restrict__ emb,
                const float* __restrict__ Wx, const float* __restrict__ bo) {
    __shared__ __align__(128) __nv_bfloat16 sAh[128 * ASTR];
    __shared__ __align__(128) __nv_bfloat16 sAl[128 * ASTR];
    __shared__ __align__(128) __nv_bfloat16 sBh[PBK * BSTR];
    __shared__ __align__(128) __nv_bfloat16 sBl[PBK * BSTR];
    __shared__ __align__(128) float sbias[16 * BSTR];
    __shared__ int ids_s[128];

    const int tid = threadIdx.x;
    const int wid = tid >> 5;
    const int bm = blockIdx.x * 128;
    const int bn = blockIdx.y * 128;
    const int wm = wid & 1;
    const int wn = wid >> 1;

    if (tid < 128) {
        ids_s[tid] = ids[bm + tid];
        float bv = bo[bn + tid];
#pragma unroll
        for (int r = 0; r < 16; r++) sbias[r * BSTR + tid] = bv;
    }
    __syncthreads();

    wmma::fragment<wmma::accumulator, 16, 16, 16, float> acc[4][2];
#pragma unroll
    for (int mi = 0; mi < 4; mi++)
#pragma unroll
        for (int ni = 0; ni < 2; ni++)
            wmma::load_matrix_sync(acc[mi][ni], sbias + wn * 32 + ni * 16, BSTR,
                                   wmma::mem_row_major);

    const int a_r = tid >> 3;
    const int a_c = (tid & 7) * 4;
    const int b_r = tid >> 5;
    const int b_c = (tid & 31) * 4;

    const float* arow_p[4];
#pragma unroll
    for (int s = 0; s < 4; s++)
        arow_p[s] = emb + (size_t)ids_s[s * 32 + a_r] * HIDDEN + a_c;

    float4 ra[4], rb[4];
#pragma unroll
    for (int s = 0; s < 4; s++) {
        ra[s] = *(const float4*)(arow_p[s]);
        rb[s] = *(const float4*)(Wx + (size_t)(s * 8 + b_r) * GATES + bn + b_c);
    }

    const int NCHUNK = HIDDEN / PBK;
#pragma unroll 1
    for (int i = 0; i < NCHUNK; i++) {
#pragma unroll
        for (int s = 0; s < 4; s++) {
            uint2 hi, lo;
            split4(ra[s], hi, lo);
            const int arow = s * 32 + a_r;
            *(uint2*)(sAh + arow * ASTR + a_c) = hi;
            *(uint2*)(sAl + arow * ASTR + a_c) = lo;
            split4(rb[s], hi, lo);
            const int brow = s * 8 + b_r;
            *(uint2*)(sBh + brow * BSTR + b_c) = hi;
            *(uint2*)(sBl + brow * BSTR + b_c) = lo;
        }
        __syncthreads();

        if (i + 1 < NCHUNK) {
            int k0 = (i + 1) * PBK;
#pragma unroll
            for (int s = 0; s < 4; s++) {
                ra[s] = *(const float4*)(arow_p[s] + k0);
                rb[s] = *(const float4*)(Wx + (size_t)(k0 + s * 8 + b_r) * GATES + bn + b_c);
            }
        }

#pragma unroll
        for (int kk = 0; kk < 2; kk++) {
            wmma::fragment<wmma::matrix_a, 16, 16, 16, __nv_bfloat16, wmma::row_major> afh[4], afl[4];
            wmma::fragment<wmma::matrix_b, 16, 16, 16, __nv_bfloat16, wmma::row_major> bfh[2], bfl[2];
#pragma unroll
            for (int mi = 0; mi < 4; mi++) {
                const int ao = (wm * 64 + mi * 16) * ASTR + kk * 16;
                wmma::load_matrix_sync(afh[mi], sAh + ao, ASTR);
                wmma::load_matrix_sync(afl[mi], sAl + ao, ASTR);
            }
#pragma unroll
            for (int ni = 0; ni < 2; ni++) {
                const int bo2 = (kk * 16) * BSTR + wn * 32 + ni * 16;
                wmma::load_matrix_sync(bfh[ni], sBh + bo2, BSTR);
                wmma::load_matrix_sync(bfl[ni], sBl + bo2, BSTR);
            }
#pragma unroll
            for (int mi = 0; mi < 4; mi++)
#pragma unroll
                for (int ni = 0; ni < 2; ni++) {
                    wmma::mma_sync(acc[mi][ni], afh[mi], bfh[ni], acc[mi][ni]);
                    wmma::mma_sync(acc[mi][ni], afh[mi], bfl[ni], acc[mi][ni]);
                    wmma::mma_sync(acc[mi][ni], afl[mi], bfh[ni], acc[mi][ni]);
                }
        }
        __syncthreads();
    }

#pragma unroll
    for (int mi = 0; mi < 4; mi++)
#pragma unroll
        for (int ni = 0; ni < 2; ni++) {
            float* op = g_XG + (size_t)(bm + wm * 64 + mi * 16) * GATES + bn + wn * 32 + ni * 16;
            wmma::store_matrix_sync(op, acc[mi][ni], GATES, wmma::mem_row_major);
        }
}

// ---- persistent LSTM: all 128 steps in ONE launch --------------------------
// 128 CTAs (1/SM guaranteed resident), 256 threads. CTA c owns units [c*8, c*8+8)
// = 32 permuted gate columns [c*32, c*32+32). Per step: 8 warps (2M x 2N x 2K-half)
// compute the 32x32 gate tile via wmma straight from global (WhP slice is L1-hot),
// reduce K-halves through smem, in-CTA pointwise, one grid barrier.
__global__ void __launch_bounds__(256, 1)
lstm_persistent_kernel() {
    __shared__ float G[2][32][36];   // [khalf][row][permuted col], ldm=36 (mult of 4)

    const int tid = threadIdx.x;
    const int wid = tid >> 5;
    const int c = blockIdx.x;            // 0..127
    const int wm = wid & 1;
    const int wn = (wid >> 1) & 1;
    const int kh = wid >> 2;             // 0..1
    const int ccol = c * 32 + wn * 16;

    const int r = tid >> 3;              // 0..31 (batch row)
    const int uu = tid & 7;              // 0..7  (unit within CTA)
    const int unit = c * 8 + uu;
    const int hidx = r * HIDDEN + unit;

#pragma unroll 1
    for (int t = 0; t < T_STEPS; t++) {
        // ---- gemm: G = h @ WhP(columns of this CTA) ----
        wmma::fragment<wmma::accumulator, 16, 16, 16, float> acc;
        wmma::fill_fragment(acc, 0.0f);
        const __nv_bfloat16* __restrict__ Ah = g_hh + (wm * 16) * HIDDEN;
        const __nv_bfloat16* __restrict__ Al = g_hl + (wm * 16) * HIDDEN;
#pragma unroll 4
        for (int kt = 0; kt < 32; kt++) {
            const int k0 = kh * 512 + kt * 16;
            wmma::fragment<wmma::matrix_a, 16, 16, 16, __nv_bfloat16, wmma::row_major> afh, afl;
            wmma::fragment<wmma::matrix_b, 16, 16, 16, __nv_bfloat16, wmma::row_major> bfh, bfl;
            wmma::load_matrix_sync(afh, Ah + k0, HIDDEN);
            wmma::load_matrix_sync(afl, Al + k0, HIDDEN);
            wmma::load_matrix_sync(bfh, g_WhPH + (size_t)k0 * GATES + ccol, GATES);
            wmma::load_matrix_sync(bfl, g_WhPL + (size_t)k0 * GATES + ccol, GATES);
            wmma::mma_sync(acc, afh, bfh, acc);
            wmma::mma_sync(acc, afh, bfl, acc);
            wmma::mma_sync(acc, afl, bfh, acc);
        }
        wmma::store_matrix_sync(&G[kh][wm * 16][wn * 16], acc, 36, wmma::mem_row_major);
        __syncthreads();

        // ---- pointwise: gates = G0 + G1 + XG[t]; cell update ----
        const float* __restrict__ XGt = g_XG + (size_t)t * BATCH * GATES + (size_t)r * GATES;
        float gate[4];
#pragma unroll
        for (int g = 0; g < 4; g++) {
            const int p = g * 8 + uu;
            gate[g] = G[0][r][p] + G[1][r][p] + XGt[unit + (g << 10)];
        }
        float cold = g_c[hidx];
        float si = 1.0f / (1.0f + expf(-gate[0]));
        float sf = 1.0f / (1.0f + expf(-gate[1]));
        float tg = tanhf(gate[2]);
        float so = 1.0f / (1.0f + expf(-gate[3]));
        float cn = sf * cold + si * tg;
        float hn = so * tanhf(cn);

        g_c[hidx] = cn;
        __nv_bfloat16 hh = __float2bfloat16(hn);
        __nv_bfloat16 hl = __float2bfloat16(hn - __bfloat162float(hh));
        g_hh[hidx] = hh;
        g_hl[hidx] = hl;
        const size_t ho = ((size_t)t * BATCH + r) * HIDDEN + unit;
        g_HSh[ho] = hh;
        g_HSl[ho] = hl;

        __syncthreads();   // all h/G traffic of this CTA done

        // ---- grid barrier (skip after last step) ----
        if (t + 1 < T_STEPS) {
            if (tid == 0) {
                __threadfence();
                atomicAdd(&g_arrive, 1u);
                const unsigned target = (unsigned)(t + 1) * gridDim.x;
                while (*(volatile unsigned*)&g_arrive < target) {}
                __threadfence();
            }
            __syncthreads();
            __threadfence();   // freshen L1 for next step's h loads
        }
    }
}

// ---- projection (R14-proven): out = HSbf16 @ Wo + bo -----------------------
__global__ void __launch_bounds__(256, 1)
gemm_wmma_proj(const float* __restrict__ Wo, const float* __restrict__ bo,
               float* __restrict__ out) {
    __shared__ __align__(128) __nv_bfloat16 sAh[128 * ASTR];
    __shared__ __align__(128) __nv_bfloat16 sAl[128 * ASTR];
    __shared__ __align__(128) __nv_bfloat16 sBh[PBK * BSTR];
    __shared__ __align__(128) __nv_bfloat16 sBl[PBK * BSTR];
    __shared__ __align__(128) float sbias[16 * BSTR];

    const int tid = threadIdx.x;
    const int wid = tid >> 5;
    const int bm = blockIdx.x * 128;
    const int bn = blockIdx.y * 128;
    const int wm = wid & 1;
    const int wn = wid >> 1;

    if (tid < 128) {
        float bv = bo[bn + tid];
#pragma unroll
        for (int r = 0; r < 16; r++) sbias[r * BSTR + tid] = bv;
    }
    __syncthreads();

    wmma::fragment<wmma::accumulator, 16, 16, 16, float> acc[4][2];
#pragma unroll
    for (int mi = 0; mi < 4; mi++)
#pragma unroll
        for (int ni = 0; ni < 2; ni++)
            wmma::load_matrix_sync(acc[mi][ni], sbias + wn * 32 + ni * 16, BSTR,
                                   wmma::mem_row_major);

    int a_r[2], a_c8[2];
#pragma unroll
    for (int it = 0; it < 2; it++) {
        int idx = tid + it * 256;
        a_r[it] = idx >> 2;
        a_c8[it] = (idx & 3) * 8;
    }
    const int b_r = tid >> 5;
    const int b_c = (tid & 31) * 4;

    uint4 rAh[2], rAl[2];
    float4 rb[4];
#pragma unroll
    for (int it = 0; it < 2; it++) {
        size_t ao = (size_t)(bm + a_r[it]) * HIDDEN + a_c8[it];
        rAh[it] = *(const uint4*)(g_HSh + ao);
        rAl[it] = *(const uint4*)(g_HSl + ao);
    }
#pragma unroll
    for (int s = 0; s < 4; s++)
        rb[s] = *(const float4*)(Wo + (size_t)(s * 8 + b_r) * NCLS + bn + b_c);

    const int NCHUNK = HIDDEN / PBK;
#pragma unroll 1
    for (int i = 0; i < NCHUNK; i++) {
#pragma unroll
        for (int it = 0; it < 2; it++) {
            *(uint4*)(sAh + a_r[it] * ASTR + a_c8[it]) = rAh[it];
            *(uint4*)(sAl + a_r[it] * ASTR + a_c8[it]) = rAl[it];
        }
#pragma unroll
        for (int s = 0; s < 4; s++) {
            uint2 hi, lo;
            split4(rb[s], hi, lo);
            const int brow = s * 8 + b_r;
            *(uint2*)(sBh + brow * BSTR + b_c) = hi;
            *(uint2*)(sBl + brow * BSTR + b_c) = lo;
        }
        __syncthreads();

        if (i + 1 < NCHUNK) {
            const int k0 = (i + 1) * PBK;
#pragma unroll
            for (int it = 0; it < 2; it++) {
                size_t ao = (size_t)(bm + a_r[it]) * HIDDEN + k0 + a_c8[it];
                rAh[it] = *(const uint4*)(g_HSh + ao);
                rAl[it] = *(const uint4*)(g_HSl + ao);
            }
#pragma unroll
            for (int s = 0; s < 4; s++)
                rb[s] = *(const float4*)(Wo + (size_t)(k0 + s * 8 + b_r) * NCLS + bn + b_c);
        }

#pragma unroll
        for (int kk = 0; kk < 2; kk++) {
            wmma::fragment<wmma::matrix_a, 16, 16, 16, __nv_bfloat16, wmma::row_major> afh[4], afl[4];
            wmma::fragment<wmma::matrix_b, 16, 16, 16, __nv_bfloat16, wmma::row_major> bfh[2], bfl[2];
#pragma unroll
            for (int mi = 0; mi < 4; mi++) {
                const int ao = (wm * 64 + mi * 16) * ASTR + kk * 16;
                wmma::load_matrix_sync(afh[mi], sAh + ao, ASTR);
                wmma::load_matrix_sync(afl[mi], sAl + ao, ASTR);
            }
#pragma unroll
            for (int ni = 0; ni < 2; ni++) {
                const int bo2 = (kk * 16) * BSTR + wn * 32 + ni * 16;
                wmma::load_matrix_sync(bfh[ni], sBh + bo2, BSTR);
                wmma::load_matrix_sync(bfl[ni], sBl + bo2, BSTR);
            }
#pragma unroll
            for (int mi = 0; mi < 4; mi++)
#pragma unroll
                for (int ni = 0; ni < 2; ni++) {
                    wmma::mma_sync(acc[mi][ni], afh[mi], bfh[ni], acc[mi][ni]);
                    wmma::mma_sync(acc[mi][ni], afh[mi], bfl[ni], acc[mi][ni]);
                    wmma::mma_sync(acc[mi][ni], afl[mi], bfh[ni], acc[mi][ni]);
                }
        }
        __syncthreads();
    }

#pragma unroll
    for (int mi = 0; mi < 4; mi++)
#pragma unroll
        for (int ni = 0; ni < 2; ni++) {
            float* op = out + (size_t)(bm + wm * 64 + mi * 16) * NCLS + bn + wn * 32 + ni * 16;
            wmma::store_matrix_sync(op, acc[mi][ni], NCLS, wmma::mem_row_major);
        }
}

// --------------------------------------------------------------------------
extern "C" void kernel_launch(void* const* d_in, const int* in_sizes, int n_in,
                              void* d_out, int out_size) {
    const int*   input = (const int*)d_in[0];
    const float* emb   = (const float*)d_in[1];
    const float* W_x   = (const float*)d_in[2];
    const float* W_h   = (const float*)d_in[3];
    const float* b     = (const float*)d_in[4];
    const float* W_h2o = (const float*)d_in[5];
    const float* b_o   = (const float*)d_in[6];
    float* out = (float*)d_out;

    (void)in_sizes; (void)n_in; (void)out_size;

    init_state_kernel<<<(BATCH * HIDDEN + 255) / 256, 256>>>();
    split_wh_perm_kernel<<<HIDDEN * 512 / 256, 256>>>(W_h);   // 2048 blocks

    {
        dim3 grid(M_ALL / 128, GATES / 128);  // (32, 32)
        gemm_wmma_embed<<<grid, 256>>>(input, emb, W_x, b);
    }

    // ---- recurrence: one persistent kernel, 128 CTAs ----
    lstm_persistent_kernel<<<128, 256>>>();

    {
        dim3 grid(M_ALL / 128, NCLS / 128);   // (32, 250)
        gemm_wmma_proj<<<grid, 256>>>(W_h2o, b_o, out);
    }
}

// round 17
// speedup vs baseline: 1.1887x; 1.1887x over previous
#include <cuda_runtime.h>
#include <cuda_bf16.h>
#include <mma.h>
#include <math.h>
#include <cstdint>

using namespace nvcuda;

#define T_STEPS 128
#define BATCH   32
#define HIDDEN  1024
#define GATES   4096     // 4*HIDDEN
#define NCLS    32000
#define M_ALL   4096     // T_STEPS*BATCH

// ---------------- scratch (~96.5 MiB, within passing regime) ----------------
__device__ float g_XG[(size_t)M_ALL * GATES];   // 64 MB
__device__ float g_c[BATCH * HIDDEN];
__device__ __align__(128) __nv_bfloat16 g_hh[BATCH * HIDDEN];
__device__ __align__(128) __nv_bfloat16 g_hl[BATCH * HIDDEN];
__device__ __align__(128) __nv_bfloat16 g_HSh[(size_t)M_ALL * HIDDEN];  // 8 MB
__device__ __align__(128) __nv_bfloat16 g_HSl[(size_t)M_ALL * HIDDEN];  // 8 MB
__device__ __align__(128) __nv_bfloat16 g_WhPH[(size_t)HIDDEN * GATES]; // 8 MB (permuted)
__device__ __align__(128) __nv_bfloat16 g_WhPL[(size_t)HIDDEN * GATES]; // 8 MB (permuted)

// ---------------- helpers: packed fp32x4 -> bf16x2 hi/lo ----------------
__device__ __forceinline__ void split4(const float4 v, uint2& hi, uint2& lo) {
    __nv_bfloat162 h01 = __floats2bfloat162_rn(v.x, v.y);
    __nv_bfloat162 h23 = __floats2bfloat162_rn(v.z, v.w);
    float2 f01 = __bfloat1622float2(h01);
    float2 f23 = __bfloat1622float2(h23);
    __nv_bfloat162 l01 = __floats2bfloat162_rn(v.x - f01.x, v.y - f01.y);
    __nv_bfloat162 l23 = __floats2bfloat162_rn(v.z - f23.x, v.w - f23.y);
    hi.x = *(uint32_t*)&h01; hi.y = *(uint32_t*)&h23;
    lo.x = *(uint32_t*)&l01; lo.y = *(uint32_t*)&l23;
}

// ---------------- init ----------------
__global__ void init_state_kernel() {
    int i = blockIdx.x * blockDim.x + threadIdx.x;
    if (i < BATCH * HIDDEN) {
        g_c[i] = 0.0f;
        g_hh[i] = __float2bfloat16(0.0f);
        g_hl[i] = __float2bfloat16(0.0f);
    }
}

// ---------------- split + permute Wh: WhP[k][c*32+g*8+u] = Wh[k][c*8+u+g*1024]
__global__ void split_wh_perm_kernel(const float* __restrict__ Wh) {
    int idx = blockIdx.x * 256 + threadIdx.x;   // 0 .. 1024*512-1
    int k = idx >> 9;          // 0..1023
    int grp = idx & 511;       // output group of 8 cols
    int c = grp >> 2, g = grp & 3;
    const float* src = Wh + (size_t)k * GATES + c * 8 + g * 1024;
    float4 v0 = *(const float4*)(src);
    float4 v1 = *(const float4*)(src + 4);
    uint2 h0, l0, h1, l1;
    split4(v0, h0, l0);
    split4(v1, h1, l1);
    uint4 hv; hv.x = h0.x; hv.y = h0.y; hv.z = h1.x; hv.w = h1.y;
    uint4 lv; lv.x = l0.x; lv.y = l0.y; lv.z = l1.x; lv.w = l1.y;
    size_t o = (size_t)k * GATES + grp * 8;
    *(uint4*)(g_WhPH + o) = hv;
    *(uint4*)(g_WhPL + o) = lv;
}

// ==================== wmma GEMM constants =========================
#define PBK   32
#define ASTR  40      // A smem row stride (elements)
#define BSTR  136     // B smem row stride (elements)

// ---- embed (R14-proven): XG = emb[ids] @ Wx + b ---------------------------
__global__ void __launch_bounds__(256, 1)
gemm_wmma_embed(const int* __restrict__ ids, const float* __restrict__ emb,
                const float* __restrict__ Wx, const float* __restrict__ bo) {
    __shared__ __align__(128) __nv_bfloat16 sAh[128 * ASTR];
    __shared__ __align__(128) __nv_bfloat16 sAl[128 * ASTR];
    __shared__ __align__(128) __nv_bfloat16 sBh[PBK * BSTR];
    __shared__ __align__(128) __nv_bfloat16 sBl[PBK * BSTR];
    __shared__ __align__(128) float sbias[16 * BSTR];
    __shared__ int ids_s[128];

    const int tid = threadIdx.x;
    const int wid = tid >> 5;
    const int bm = blockIdx.x * 128;
    const int bn = blockIdx.y * 128;
    const int wm = wid & 1;
    const int wn = wid >> 1;

    if (tid < 128) {
        ids_s[tid] = ids[bm + tid];
        float bv = bo[bn + tid];
#pragma unroll
        for (int r = 0; r < 16; r++) sbias[r * BSTR + tid] = bv;
    }
    __syncthreads();

    wmma::fragment<wmma::accumulator, 16, 16, 16, float> acc[4][2];
#pragma unroll
    for (int mi = 0; mi < 4; mi++)
#pragma unroll
        for (int ni = 0; ni < 2; ni++)
            wmma::load_matrix_sync(acc[mi][ni], sbias + wn * 32 + ni * 16, BSTR,
                                   wmma::mem_row_major);

    const int a_r = tid >> 3;
    const int a_c = (tid & 7) * 4;
    const int b_r = tid >> 5;
    const int b_c = (tid & 31) * 4;

    const float* arow_p[4];
#pragma unroll
    for (int s = 0; s < 4; s++)
        arow_p[s] = emb + (size_t)ids_s[s * 32 + a_r] * HIDDEN + a_c;

    float4 ra[4], rb[4];
#pragma unroll
    for (int s = 0; s < 4; s++) {
        ra[s] = *(const float4*)(arow_p[s]);
        rb[s] = *(const float4*)(Wx + (size_t)(s * 8 + b_r) * GATES + bn + b_c);
    }

    const int NCHUNK = HIDDEN / PBK;
#pragma unroll 1
    for (int i = 0; i < NCHUNK; i++) {
#pragma unroll
        for (int s = 0; s < 4; s++) {
            uint2 hi, lo;
            split4(ra[s], hi, lo);
            const int arow = s * 32 + a_r;
            *(uint2*)(sAh + arow * ASTR + a_c) = hi;
            *(uint2*)(sAl + arow * ASTR + a_c) = lo;
            split4(rb[s], hi, lo);
            const int brow = s * 8 + b_r;
            *(uint2*)(sBh + brow * BSTR + b_c) = hi;
            *(uint2*)(sBl + brow * BSTR + b_c) = lo;
        }
        __syncthreads();

        if (i + 1 < NCHUNK) {
            int k0 = (i + 1) * PBK;
#pragma unroll
            for (int s = 0; s < 4; s++) {
                ra[s] = *(const float4*)(arow_p[s] + k0);
                rb[s] = *(const float4*)(Wx + (size_t)(k0 + s * 8 + b_r) * GATES + bn + b_c);
            }
        }

#pragma unroll
        for (int kk = 0; kk < 2; kk++) {
            wmma::fragment<wmma::matrix_a, 16, 16, 16, __nv_bfloat16, wmma::row_major> afh[4], afl[4];
            wmma::fragment<wmma::matrix_b, 16, 16, 16, __nv_bfloat16, wmma::row_major> bfh[2], bfl[2];
#pragma unroll
            for (int mi = 0; mi < 4; mi++) {
                const int ao = (wm * 64 + mi * 16) * ASTR + kk * 16;
                wmma::load_matrix_sync(afh[mi], sAh + ao, ASTR);
                wmma::load_matrix_sync(afl[mi], sAl + ao, ASTR);
            }
#pragma unroll
            for (int ni = 0; ni < 2; ni++) {
                const int bo2 = (kk * 16) * BSTR + wn * 32 + ni * 16;
                wmma::load_matrix_sync(bfh[ni], sBh + bo2, BSTR);
                wmma::load_matrix_sync(bfl[ni], sBl + bo2, BSTR);
            }
#pragma unroll
            for (int mi = 0; mi < 4; mi++)
#pragma unroll
                for (int ni = 0; ni < 2; ni++) {
                    wmma::mma_sync(acc[mi][ni], afh[mi], bfh[ni], acc[mi][ni]);
                    wmma::mma_sync(acc[mi][ni], afh[mi], bfl[ni], acc[mi][ni]);
                    wmma::mma_sync(acc[mi][ni], afl[mi], bfh[ni], acc[mi][ni]);
                }
        }
        __syncthreads();
    }

#pragma unroll
    for (int mi = 0; mi < 4; mi++)
#pragma unroll
        for (int ni = 0; ni < 2; ni++) {
            float* op = g_XG + (size_t)(bm + wm * 64 + mi * 16) * GATES + bn + wn * 32 + ni * 16;
            wmma::store_matrix_sync(op, acc[mi][ni], GATES, wmma::mem_row_major);
        }
}

// ---- fused per-step LSTM: gemm (32x32xK=1024, permuted cols) + pointwise ---
// 128 CTAs, 256 threads = 8 warps: (wm 2) x (wn 2) x (kh 2 K-halves).
// smem-staged, register-prefetch loads (R14-proven pattern); K-halves reduced
// through smem; in-CTA pointwise. No partials kernel, 1 launch per step.
#define LSTR 40

__global__ void __launch_bounds__(256, 1)
lstm_step_fused(int t) {
    __shared__ __align__(128) __nv_bfloat16 sAh[2][32 * LSTR];
    __shared__ __align__(128) __nv_bfloat16 sAl[2][32 * LSTR];
    __shared__ __align__(128) __nv_bfloat16 sBh[2][32 * LSTR];
    __shared__ __align__(128) __nv_bfloat16 sBl[2][32 * LSTR];
    __shared__ float G[2][32][36];

    const int tid = threadIdx.x;
    const int wid = tid >> 5;
    const int c = blockIdx.x;            // 0..127: owns permuted cols [c*32, c*32+32)
    const int wm = wid & 1;
    const int wn = (wid >> 1) & 1;
    const int kh = wid >> 2;             // 0..1

    // load coords: 256 threads cover [2 ranges][32 rows][4 x 8-elem groups]
    const int rg = tid >> 7;             // K-half this thread loads for
    const int lrow = (tid >> 2) & 31;    // A: M row;  B: K row within chunk
    const int c8 = (tid & 3) * 8;

    const __nv_bfloat16* __restrict__ ah_p = g_hh + lrow * HIDDEN + rg * 512 + c8;
    const __nv_bfloat16* __restrict__ al_p = g_hl + lrow * HIDDEN + rg * 512 + c8;
    const size_t b_base = (size_t)(rg * 512 + lrow) * GATES + c * 32 + c8;

    wmma::fragment<wmma::accumulator, 16, 16, 16, float> acc;
    wmma::fill_fragment(acc, 0.0f);

    // prologue: chunk 0
    uint4 rAh = *(const uint4*)(ah_p);
    uint4 rAl = *(const uint4*)(al_p);
    uint4 rBh = *(const uint4*)(g_WhPH + b_base);
    uint4 rBl = *(const uint4*)(g_WhPL + b_base);

    const int NCHUNK = 512 / PBK;        // 16 chunks of 32 K per half
#pragma unroll 1
    for (int i = 0; i < NCHUNK; i++) {
        *(uint4*)(sAh[rg] + lrow * LSTR + c8) = rAh;
        *(uint4*)(sAl[rg] + lrow * LSTR + c8) = rAl;
        *(uint4*)(sBh[rg] + lrow * LSTR + c8) = rBh;
        *(uint4*)(sBl[rg] + lrow * LSTR + c8) = rBl;
        __syncthreads();

        if (i + 1 < NCHUNK) {
            const int k0 = (i + 1) * PBK;
            rAh = *(const uint4*)(ah_p + k0);
            rAl = *(const uint4*)(al_p + k0);
            rBh = *(const uint4*)(g_WhPH + b_base + (size_t)k0 * GATES);
            rBl = *(const uint4*)(g_WhPL + b_base + (size_t)k0 * GATES);
        }

#pragma unroll
        for (int kk = 0; kk < 2; kk++) {
            wmma::fragment<wmma::matrix_a, 16, 16, 16, __nv_bfloat16, wmma::row_major> afh, afl;
            wmma::fragment<wmma::matrix_b, 16, 16, 16, __nv_bfloat16, wmma::row_major> bfh, bfl;
            const int ao = (wm * 16) * LSTR + kk * 16;
            const int bo2 = (kk * 16) * LSTR + wn * 16;
            wmma::load_matrix_sync(afh, sAh[kh] + ao, LSTR);
            wmma::load_matrix_sync(afl, sAl[kh] + ao, LSTR);
            wmma::load_matrix_sync(bfh, sBh[kh] + bo2, LSTR);
            wmma::load_matrix_sync(bfl, sBl[kh] + bo2, LSTR);
            wmma::mma_sync(acc, afh, bfh, acc);
            wmma::mma_sync(acc, afh, bfl, acc);
            wmma::mma_sync(acc, afl, bfh, acc);
        }
        __syncthreads();
    }

    wmma::store_matrix_sync(&G[kh][wm * 16][wn * 16], acc, 36, wmma::mem_row_major);
    __syncthreads();

    // ---- pointwise: gates = G0 + G1 + XG[t]; cell update ----
    const int r = tid >> 3;              // batch row 0..31
    const int uu = tid & 7;              // unit within CTA
    const int unit = c * 8 + uu;
    const int hidx = r * HIDDEN + unit;
    const float* __restrict__ XGt = g_XG + (size_t)t * BATCH * GATES + (size_t)r * GATES;

    float gate[4];
#pragma unroll
    for (int g = 0; g < 4; g++) {
        const int p = g * 8 + uu;
        gate[g] = G[0][r][p] + G[1][r][p] + XGt[unit + (g << 10)];
    }
    float cold = g_c[hidx];
    float si = 1.0f / (1.0f + expf(-gate[0]));
    float sf = 1.0f / (1.0f + expf(-gate[1]));
    float tg = tanhf(gate[2]);
    float so = 1.0f / (1.0f + expf(-gate[3]));
    float cn = sf * cold + si * tg;
    float hn = so * tanhf(cn);

    g_c[hidx] = cn;
    __nv_bfloat16 hh = __float2bfloat16(hn);
    __nv_bfloat16 hl = __float2bfloat16(hn - __bfloat162float(hh));
    g_hh[hidx] = hh;
    g_hl[hidx] = hl;
    const size_t ho = ((size_t)t * BATCH + r) * HIDDEN + unit;
    g_HSh[ho] = hh;
    g_HSl[ho] = hl;
}

// ---- projection (R14-proven): out = HSbf16 @ Wo + bo -----------------------
__global__ void __launch_bounds__(256, 1)
gemm_wmma_proj(const float* __restrict__ Wo, const float* __restrict__ bo,
               float* __restrict__ out) {
    __shared__ __align__(128) __nv_bfloat16 sAh[128 * ASTR];
    __shared__ __align__(128) __nv_bfloat16 sAl[128 * ASTR];
    __shared__ __align__(128) __nv_bfloat16 sBh[PBK * BSTR];
    __shared__ __align__(128) __nv_bfloat16 sBl[PBK * BSTR];
    __shared__ __align__(128) float sbias[16 * BSTR];

    const int tid = threadIdx.x;
    const int wid = tid >> 5;
    const int bm = blockIdx.x * 128;
    const int bn = blockIdx.y * 128;
    const int wm = wid & 1;
    const int wn = wid >> 1;

    if (tid < 128) {
        float bv = bo[bn + tid];
#pragma unroll
        for (int r = 0; r < 16; r++) sbias[r * BSTR + tid] = bv;
    }
    __syncthreads();

    wmma::fragment<wmma::accumulator, 16, 16, 16, float> acc[4][2];
#pragma unroll
    for (int mi = 0; mi < 4; mi++)
#pragma unroll
        for (int ni = 0; ni < 2; ni++)
            wmma::load_matrix_sync(acc[mi][ni], sbias + wn * 32 + ni * 16, BSTR,
                                   wmma::mem_row_major);

    int a_r[2], a_c8[2];
#pragma unroll
    for (int it = 0; it < 2; it++) {
        int idx = tid + it * 256;
        a_r[it] = idx >> 2;
        a_c8[it] = (idx & 3) * 8;
    }
    const int b_r = tid >> 5;
    const int b_c = (tid & 31) * 4;

    uint4 rAh[2], rAl[2];
    float4 rb[4];
#pragma unroll
    for (int it = 0; it < 2; it++) {
        size_t ao = (size_t)(bm + a_r[it]) * HIDDEN + a_c8[it];
        rAh[it] = *(const uint4*)(g_HSh + ao);
        rAl[it] = *(const uint4*)(g_HSl + ao);
    }
#pragma unroll
    for (int s = 0; s < 4; s++)
        rb[s] = *(const float4*)(Wo + (size_t)(s * 8 + b_r) * NCLS + bn + b_c);

    const int NCHUNK = HIDDEN / PBK;
#pragma unroll 1
    for (int i = 0; i < NCHUNK; i++) {
#pragma unroll
        for (int it = 0; it < 2; it++) {
            *(uint4*)(sAh + a_r[it] * ASTR + a_c8[it]) = rAh[it];
            *(uint4*)(sAl + a_r[it] * ASTR + a_c8[it]) = rAl[it];
        }
#pragma unroll
        for (int s = 0; s < 4; s++) {
            uint2 hi, lo;
            split4(rb[s], hi, lo);
            const int brow = s * 8 + b_r;
            *(uint2*)(sBh + brow * BSTR + b_c) = hi;
            *(uint2*)(sBl + brow * BSTR + b_c) = lo;
        }
        __syncthreads();

        if (i + 1 < NCHUNK) {
            const int k0 = (i + 1) * PBK;
#pragma unroll
            for (int it = 0; it < 2; it++) {
                size_t ao = (size_t)(bm + a_r[it]) * HIDDEN + k0 + a_c8[it];
                rAh[it] = *(const uint4*)(g_HSh + ao);
                rAl[it] = *(const uint4*)(g_HSl + ao);
            }
#pragma unroll
            for (int s = 0; s < 4; s++)
                rb[s] = *(const float4*)(Wo + (size_t)(k0 + s * 8 + b_r) * NCLS + bn + b_c);
        }

#pragma unroll
        for (int kk = 0; kk < 2; kk++) {
            wmma::fragment<wmma::matrix_a, 16, 16, 16, __nv_bfloat16, wmma::row_major> afh[4], afl[4];
            wmma::fragment<wmma::matrix_b, 16, 16, 16, __nv_bfloat16, wmma::row_major> bfh[2], bfl[2];
#pragma unroll
            for (int mi = 0; mi < 4; mi++) {
                const int ao = (wm * 64 + mi * 16) * ASTR + kk * 16;
                wmma::load_matrix_sync(afh[mi], sAh + ao, ASTR);
                wmma::load_matrix_sync(afl[mi], sAl + ao, ASTR);
            }
#pragma unroll
            for (int ni = 0; ni < 2; ni++) {
                const int bo2 = (kk * 16) * BSTR + wn * 32 + ni * 16;
                wmma::load_matrix_sync(bfh[ni], sBh + bo2, BSTR);
                wmma::load_matrix_sync(bfl[ni], sBl + bo2, BSTR);
            }
#pragma unroll
            for (int mi = 0; mi < 4; mi++)
#pragma unroll
                for (int ni = 0; ni < 2; ni++) {
                    wmma::mma_sync(acc[mi][ni], afh[mi], bfh[ni], acc[mi][ni]);
                    wmma::mma_sync(acc[mi][ni], afh[mi], bfl[ni], acc[mi][ni]);
                    wmma::mma_sync(acc[mi][ni], afl[mi], bfh[ni], acc[mi][ni]);
                }
        }
        __syncthreads();
    }

#pragma unroll
    for (int mi = 0; mi < 4; mi++)
#pragma unroll
        for (int ni = 0; ni < 2; ni++) {
            float* op = out + (size_t)(bm + wm * 64 + mi * 16) * NCLS + bn + wn * 32 + ni * 16;
            wmma::store_matrix_sync(op, acc[mi][ni], NCLS, wmma::mem_row_major);
        }
}

// --------------------------------------------------------------------------
extern "C" void kernel_launch(void* const* d_in, const int* in_sizes, int n_in,
                              void* d_out, int out_size) {
    const int*   input = (const int*)d_in[0];
    const float* emb   = (const float*)d_in[1];
    const float* W_x   = (const float*)d_in[2];
    const float* W_h   = (const float*)d_in[3];
    const float* b     = (const float*)d_in[4];
    const float* W_h2o = (const float*)d_in[5];
    const float* b_o   = (const float*)d_in[6];
    float* out = (float*)d_out;

    (void)in_sizes; (void)n_in; (void)out_size;

    init_state_kernel<<<(BATCH * HIDDEN + 255) / 256, 256>>>();
    split_wh_perm_kernel<<<HIDDEN * 512 / 256, 256>>>(W_h);

    {
        dim3 grid(M_ALL / 128, GATES / 128);  // (32, 32)
        gemm_wmma_embed<<<grid, 256>>>(input, emb, W_x, b);
    }

    for (int t = 0; t < T_STEPS; t++)
        lstm_step_fused<<<128, 256>>>(t);     // 1 launch per step

    {
        dim3 grid(M_ALL / 128, NCLS / 128);   // (32, 250)
        gemm_wmma_proj<<<grid, 256>>>(W_h2o, b_o, out);
    }
}